// round 1
// baseline (speedup 1.0000x reference)
#include <cuda_runtime.h>
#include <cstdint>
#include <math.h>

// ---------------------------------------------------------------------------
// GCODERNN: graph-ODE RNN.
//   B=8, T=32, N=1024, DIM_IN=64, DIM_RNN=DIM_ODE=128, DT=0.25
// Structure:
//   precompute X = values*masks; AX[t,b] = A[b] @ X[b,t]   (input side of GRU)
//   recurrence: per step 5 sequential batched GEMMs A[8,1024,1024]@[8,1024,128]
//   small dense 128x128 / 192x128 GEMMs fused with nonlinearities (PT kernels)
// ---------------------------------------------------------------------------

#define BB   8
#define TT   32
#define NN   1024
#define DIN  64
#define DR   128
#define DT_C 0.25f

// ------------------------- device scratch (no allocs) ----------------------
__device__ float g_X  [BB*TT*NN*DIN];   // values*masks, [B,T,N,64]
__device__ float g_AX [TT*BB*NN*DIN];   // A@x, [T,B,N,64]
__device__ float g_H  [BB*NN*DR];
__device__ float g_HV1[BB*NN*DR];
__device__ float g_U  [BB*NN*DR];
__device__ float g_G  [BB*NN*DR];
__device__ float g_Z  [BB*NN*DR];
__device__ float g_RH [BB*NN*DR];
__device__ float g_OBS[TT*BB];          // [T,B] observation flags

// ---------------------------------------------------------------------------
// ag_kernel: C[z] = A[z/a_div] @ Bsrc[z],  M=K=1024, N-cols = DN (64 or 128)
// tile 64x64, 256 threads, 4x4 per thread, K-chunk 32.
// c_perm: remap output batch z=(b*a_div+t) -> cz=(t*(Z/a_div)+b)  (for AX)
// ---------------------------------------------------------------------------
template<int DN>
__global__ void __launch_bounds__(256) ag_kernel(
    const float* __restrict__ Aall, const float* __restrict__ Ball,
    float* __restrict__ Call, int a_div, int c_perm)
{
    __shared__ float As[64][33];   // padded: conflict-free scalar reads
    __shared__ float Bs[32][64];   // unpadded: float4 reads

    const int z = blockIdx.z;
    const float* A  = Aall + (size_t)(z / a_div) * (NN * NN);
    const float* Bm = Ball + (size_t)z * (NN * DN);
    const int cz = c_perm ? ((z % a_div) * (gridDim.z / a_div) + z / a_div) : z;
    float* C = Call + (size_t)cz * (NN * DN);

    const int tm = blockIdx.x * 64;
    const int tn = blockIdx.y * 64;
    const int tid = threadIdx.x;
    const int ty = tid >> 4, tx = tid & 15;

    float acc[4][4] = {};

    for (int k0 = 0; k0 < NN; k0 += 32) {
        // load A tile 64x32 (row-major, padded smem)
        #pragma unroll
        for (int l = 0; l < 2; l++) {
            int f = tid + l * 256;          // 0..511 float4s
            int r = f >> 3, c4 = f & 7;
            float4 v = *(const float4*)(A + (size_t)(tm + r) * NN + k0 + c4 * 4);
            As[r][c4*4+0] = v.x; As[r][c4*4+1] = v.y;
            As[r][c4*4+2] = v.z; As[r][c4*4+3] = v.w;
        }
        // load B tile 32x64
        #pragma unroll
        for (int l = 0; l < 2; l++) {
            int f = tid + l * 256;
            int r = f >> 4, c4 = f & 15;
            *(float4*)&Bs[r][c4*4] =
                *(const float4*)(Bm + (size_t)(k0 + r) * DN + tn + c4 * 4);
        }
        __syncthreads();
        #pragma unroll
        for (int k = 0; k < 32; k++) {
            float a0 = As[ty*4+0][k], a1 = As[ty*4+1][k];
            float a2 = As[ty*4+2][k], a3 = As[ty*4+3][k];
            float4 b = *(const float4*)&Bs[k][tx*4];
            acc[0][0] += a0*b.x; acc[0][1] += a0*b.y; acc[0][2] += a0*b.z; acc[0][3] += a0*b.w;
            acc[1][0] += a1*b.x; acc[1][1] += a1*b.y; acc[1][2] += a1*b.z; acc[1][3] += a1*b.w;
            acc[2][0] += a2*b.x; acc[2][1] += a2*b.y; acc[2][2] += a2*b.z; acc[2][3] += a2*b.w;
            acc[3][0] += a3*b.x; acc[3][1] += a3*b.y; acc[3][2] += a3*b.z; acc[3][3] += a3*b.w;
        }
        __syncthreads();
    }
    #pragma unroll
    for (int i = 0; i < 4; i++) {
        float4 v = make_float4(acc[i][0], acc[i][1], acc[i][2], acc[i][3]);
        *(float4*)(C + (size_t)(tm + ty*4 + i) * DN + tn + tx*4) = v;
    }
}

// ---------------------------------------------------------------------------
// pt_kernel: fused small GEMM + epilogue.
//   out[row,d] = epi( bias[d] + sum_k in(row,k)*W[k,d] )
//   in(row,k): k < d0 -> in0[row*d0+k] else in1[row*d1+(k-d0)]   (concat)
// modes: 0 tanh -> U | 2 hv1 = aux0 + v*DT | 3 z=sigmoid | 4 RH=sigmoid*aux0
//        5 h = obs-blend((1-z)hv1 + z*tanh(v), hv1) | 6 output head (indexed)
// tile: 64 rows x 64 cols per CTA, K-chunk 64.
// ---------------------------------------------------------------------------
__global__ void __launch_bounds__(256) pt_kernel(
    const float* __restrict__ in0, int d0,
    const float* __restrict__ in1, int d1,
    const float* __restrict__ W, const float* __restrict__ bias,
    int Kd, int Dout,
    float* __restrict__ outp,
    int mode, int tstep,
    const float* __restrict__ aux0,
    const float* __restrict__ aux1,
    const float* __restrict__ obs_t)
{
    __shared__ float Gs[64][65];
    __shared__ float Ws[64][64];

    const int row0 = blockIdx.x * 64;
    const int dc0  = blockIdx.y * 64;
    const int tid = threadIdx.x;
    const int ty = tid >> 4, tx = tid & 15;

    float acc[4][4] = {};

    for (int k0 = 0; k0 < Kd; k0 += 64) {
        const float* src; int stride, koff;
        if (k0 < d0) { src = in0; stride = d0; koff = k0; }
        else         { src = in1; stride = d1; koff = k0 - d0; }
        // Gs: 64 rows x 64 k
        #pragma unroll
        for (int l = 0; l < 4; l++) {
            int f = tid + l * 256;          // 1024 float4s
            int r = f >> 4, c4 = f & 15;
            float4 v = *(const float4*)(src + (size_t)(row0 + r) * stride + koff + c4*4);
            Gs[r][c4*4+0] = v.x; Gs[r][c4*4+1] = v.y;
            Gs[r][c4*4+2] = v.z; Gs[r][c4*4+3] = v.w;
        }
        // Ws: 64 k x 64 cols
        #pragma unroll
        for (int l = 0; l < 4; l++) {
            int f = tid + l * 256;
            int r = f >> 4, c4 = f & 15;
            *(float4*)&Ws[r][c4*4] =
                *(const float4*)(W + (size_t)(k0 + r) * Dout + dc0 + c4*4);
        }
        __syncthreads();
        #pragma unroll
        for (int k = 0; k < 64; k++) {
            float a0 = Gs[ty*4+0][k], a1 = Gs[ty*4+1][k];
            float a2 = Gs[ty*4+2][k], a3 = Gs[ty*4+3][k];
            float4 b = *(const float4*)&Ws[k][tx*4];
            acc[0][0] += a0*b.x; acc[0][1] += a0*b.y; acc[0][2] += a0*b.z; acc[0][3] += a0*b.w;
            acc[1][0] += a1*b.x; acc[1][1] += a1*b.y; acc[1][2] += a1*b.z; acc[1][3] += a1*b.w;
            acc[2][0] += a2*b.x; acc[2][1] += a2*b.y; acc[2][2] += a2*b.z; acc[2][3] += a2*b.w;
            acc[3][0] += a3*b.x; acc[3][1] += a3*b.y; acc[3][2] += a3*b.z; acc[3][3] += a3*b.w;
        }
        __syncthreads();
    }

    const int dbase = dc0 + tx * 4;
    float4 bv = *(const float4*)(bias + dbase);
    float bb[4] = {bv.x, bv.y, bv.z, bv.w};

    #pragma unroll
    for (int i = 0; i < 4; i++) {
        int row = row0 + ty * 4 + i;
        #pragma unroll
        for (int j = 0; j < 4; j++) {
            int dg = dbase + j;
            float v = acc[i][j] + bb[j];
            size_t idx = (size_t)row * Dout + dg;
            float o;
            if (mode == 0) {
                o = tanhf(v);
            } else if (mode == 2) {
                o = aux0[idx] + v * DT_C;
            } else if (mode == 3) {
                o = 1.f / (1.f + expf(-v));
            } else if (mode == 4) {
                o = (1.f / (1.f + expf(-v))) * aux0[idx];
            } else if (mode == 5) {
                float c  = tanhf(v);
                float zz = aux0[idx];
                float h1 = aux1[idx];
                float ob = obs_t[row >> 10];
                float hv2 = (1.f - zz) * h1 + zz * c;
                o = h1 * (1.f - ob) + hv2 * ob;
            } else { // mode 6: out[b, t-1, n, dg]
                o = v;
                idx = ((size_t)((row >> 10) * (TT - 1) + (tstep - 1)) * NN
                       + (row & (NN - 1))) * DIN + dg;
            }
            outp[idx] = o;
        }
    }
}

// --------------------------- small utility kernels -------------------------
__global__ void __launch_bounds__(256) xmask_kernel(
    const float4* __restrict__ v, const float4* __restrict__ m, float4* __restrict__ x)
{
    int i = blockIdx.x * 256 + threadIdx.x;
    float4 a = v[i], b = m[i];
    x[i] = make_float4(a.x*b.x, a.y*b.y, a.z*b.z, a.w*b.w);
}

__global__ void __launch_bounds__(256) inith_kernel(
    const float* __restrict__ h0, float* __restrict__ H)
{
    int i = blockIdx.x * 256 + threadIdx.x;
    H[i] = h0[i & (DR - 1)];
}

__global__ void __launch_bounds__(256) obs_kernel(
    const float* __restrict__ masks, float* __restrict__ obs)
{
    __shared__ float sh[256];
    int bt = blockIdx.x;                       // b*T + t
    const float* p = masks + (size_t)bt * (NN * DIN);
    float s = 0.f;
    for (int i = threadIdx.x; i < NN * DIN; i += 256) s += fabsf(p[i]);
    sh[threadIdx.x] = s; __syncthreads();
    for (int o = 128; o > 0; o >>= 1) {
        if (threadIdx.x < o) sh[threadIdx.x] += sh[threadIdx.x + o];
        __syncthreads();
    }
    if (threadIdx.x == 0) {
        int b = bt >> 5, t = bt & 31;
        obs[t * BB + b] = (sh[0] > 1e-4f) ? 1.f : 0.f;
    }
}

// ------------------------------- launch ------------------------------------
extern "C" void kernel_launch(void* const* d_in, const int* in_sizes, int n_in,
                              void* d_out, int out_size)
{
    const float* values = (const float*)d_in[0];
    const float* masks  = (const float*)d_in[1];
    const float* A      = (const float*)d_in[2];
    const float* h0     = (const float*)d_in[3];
    const float* W0  = (const float*)d_in[4];  const float* b0v = (const float*)d_in[5];
    const float* W1  = (const float*)d_in[6];  const float* b1v = (const float*)d_in[7];
    const float* Wou = (const float*)d_in[8];  const float* bou = (const float*)d_in[9];
    const float* Wz  = (const float*)d_in[10]; const float* bz  = (const float*)d_in[11];
    const float* Wr  = (const float*)d_in[12]; const float* br  = (const float*)d_in[13];
    const float* Wh  = (const float*)d_in[14]; const float* bh  = (const float*)d_in[15];
    const float* Wo  = (const float*)d_in[16]; const float* bo  = (const float*)d_in[17];
    float* out = (float*)d_out;

    float *X, *AX, *H, *HV1, *U, *G, *Z, *RH, *OBS;
    cudaGetSymbolAddress((void**)&X,   g_X);
    cudaGetSymbolAddress((void**)&AX,  g_AX);
    cudaGetSymbolAddress((void**)&H,   g_H);
    cudaGetSymbolAddress((void**)&HV1, g_HV1);
    cudaGetSymbolAddress((void**)&U,   g_U);
    cudaGetSymbolAddress((void**)&G,   g_G);
    cudaGetSymbolAddress((void**)&Z,   g_Z);
    cudaGetSymbolAddress((void**)&RH,  g_RH);
    cudaGetSymbolAddress((void**)&OBS, g_OBS);

    // --- precompute ---
    xmask_kernel<<<(BB*TT*NN*DIN)/4/256, 256>>>(
        (const float4*)values, (const float4*)masks, (float4*)X);
    obs_kernel<<<BB*TT, 256>>>(masks, OBS);
    // AX[t,b] = A[b] @ X[b,t]  (batched over z = b*32+t)
    ag_kernel<DIN><<<dim3(NN/64, 1, BB*TT), 256>>>(A, X, AX, TT, 1);
    inith_kernel<<<(BB*NN*DR)/256, 256>>>(h0, H);

    auto AG = [&](const float* Bin, float* Cout) {
        ag_kernel<DR><<<dim3(NN/64, DR/64, BB), 256>>>(A, Bin, Cout, 1, 0);
    };
    auto PT = [&](const float* in0, int d0, const float* in1, int d1,
                  const float* W, const float* bias, int Kd, int Dout, float* o,
                  int mode, int t, const float* a0, const float* a1, const float* ob) {
        pt_kernel<<<dim3((BB*NN)/64, Dout/64), 256>>>(
            in0, d0, in1, d1, W, bias, Kd, Dout, o, mode, t, a0, a1, ob);
    };
    auto ODE = [&](float* hin, float* hout) {
        AG(hin, G); PT(G, DR, nullptr, 0, W0,  b0v, DR, DR, U,    0, 0, nullptr, nullptr, nullptr);
        AG(U,   G); PT(G, DR, nullptr, 0, W1,  b1v, DR, DR, U,    0, 0, nullptr, nullptr, nullptr);
        AG(U,   G); PT(G, DR, nullptr, 0, Wou, bou, DR, DR, hout, 2, 0, hin,     nullptr, nullptr);
    };

    // iteration 0: h = h + ode(h)*DT
    ODE(H, H);

    for (int t = 0; t < TT; t++) {
        // hv1 = h + ode(h)*DT
        ODE(H, HV1);
        // output head: X_pred[:, t-1] = hv1 @ Wo + bo (only t>=1 is returned)
        if (t >= 1)
            PT(HV1, DR, nullptr, 0, Wo, bo, DR, DIN, out, 6, t, nullptr, nullptr, nullptr);
        // GRU update (skip at last step: its result is never used)
        if (t < TT - 1) {
            AG(HV1, G);
            const float* AXt = AX + (size_t)t * BB * NN * DIN;
            PT(AXt, DIN, G, DR, Wz, bz, DIN + DR, DR, Z,  3, t, nullptr, nullptr, nullptr);
            PT(AXt, DIN, G, DR, Wr, br, DIN + DR, DR, RH, 4, t, HV1,     nullptr, nullptr);
            AG(RH, G);
            PT(AXt, DIN, G, DR, Wh, bh, DIN + DR, DR, H,  5, t, Z, HV1, OBS + t * BB);
        }
    }
}

// round 3
// speedup vs baseline: 1.6129x; 1.6129x over previous
#include <cuda_runtime.h>
#include <cuda_bf16.h>
#include <cstdint>
#include <math.h>

// ---------------------------------------------------------------------------
// GCODERNN on GB300, compute_103-safe tensor cores:
//   A-GEMMs (A[8,1024,1024] @ H[8,1024,DN]) via warp-level mma.sync bf16
//   (m16n8k16) with split-bf16 (hi/lo) x3 emulated-fp32.
//   Small dense GEMMs + nonlinearities stay in fused fp32 SIMT PT kernels;
//   PT epilogues emit bf16 hi/lo for the next A-GEMM (no convert kernels).
// ---------------------------------------------------------------------------

#define BB   8
#define TT   32
#define NN   1024
#define DIN  64
#define DR   128
#define DT_C 0.25f

typedef __nv_bfloat16 bf16;

// ------------------------- device scratch (no allocs) ----------------------
__device__ bf16  g_Ahi[(size_t)BB*NN*NN];
__device__ bf16  g_Alo[(size_t)BB*NN*NN];
__device__ bf16  g_Xhi[(size_t)BB*TT*NN*DIN];
__device__ bf16  g_Xlo[(size_t)BB*TT*NN*DIN];
__device__ float g_AX [(size_t)TT*BB*NN*DIN];
__device__ float g_H  [BB*NN*DR];  __device__ bf16 g_Hhi [BB*NN*DR];  __device__ bf16 g_Hlo [BB*NN*DR];
__device__ float g_HV1[BB*NN*DR];  __device__ bf16 g_HV1hi[BB*NN*DR]; __device__ bf16 g_HV1lo[BB*NN*DR];
__device__ float g_U  [BB*NN*DR];  __device__ bf16 g_Uhi [BB*NN*DR];  __device__ bf16 g_Ulo [BB*NN*DR];
__device__ float g_RH [BB*NN*DR];  __device__ bf16 g_RHhi[BB*NN*DR];  __device__ bf16 g_RHlo[BB*NN*DR];
__device__ float g_G  [BB*NN*DR];
__device__ float g_Z  [BB*NN*DR];
__device__ float g_OBS[TT*BB];

// ----------------------------- PTX helpers ---------------------------------
__device__ __forceinline__ unsigned smem_u32(const void* p) {
    unsigned a;
    asm("{ .reg .u64 t; cvta.to.shared.u64 t, %1; cvt.u32.u64 %0, t; }"
        : "=r"(a) : "l"(p));
    return a;
}
__device__ __forceinline__ void ldm_x4(unsigned& r0, unsigned& r1,
                                       unsigned& r2, unsigned& r3, unsigned a) {
    asm volatile("ldmatrix.sync.aligned.m8n8.x4.shared.b16 {%0,%1,%2,%3}, [%4];"
                 : "=r"(r0), "=r"(r1), "=r"(r2), "=r"(r3) : "r"(a));
}
__device__ __forceinline__ void ldm_x2t(unsigned& r0, unsigned& r1, unsigned a) {
    asm volatile("ldmatrix.sync.aligned.m8n8.x2.trans.shared.b16 {%0,%1}, [%2];"
                 : "=r"(r0), "=r"(r1) : "r"(a));
}
__device__ __forceinline__ void mma_bf16(float* c, const unsigned* A, const unsigned* B) {
    asm volatile(
        "mma.sync.aligned.m16n8k16.row.col.f32.bf16.bf16.f32 "
        "{%0,%1,%2,%3}, {%4,%5,%6,%7}, {%8,%9}, {%0,%1,%2,%3};"
        : "+f"(c[0]), "+f"(c[1]), "+f"(c[2]), "+f"(c[3])
        : "r"(A[0]), "r"(A[1]), "r"(A[2]), "r"(A[3]), "r"(B[0]), "r"(B[1]));
}

// ---------------------------------------------------------------------------
// convA: fp32 A -> bf16 hi/lo, row-major. One block per row.
// ---------------------------------------------------------------------------
__global__ void __launch_bounds__(256) convA_kernel(const float* __restrict__ A)
{
    const size_t r = blockIdx.x;                    // 0 .. 8191
    const float* src = A + r * NN;
    bf16* dhi = g_Ahi + r * NN;
    bf16* dlo = g_Alo + r * NN;
    int i = threadIdx.x * 4;
    float4 v = *(const float4*)(src + i);
    bf16 hx = __float2bfloat16(v.x), hy = __float2bfloat16(v.y);
    bf16 hz = __float2bfloat16(v.z), hw = __float2bfloat16(v.w);
    dhi[i+0] = hx; dhi[i+1] = hy; dhi[i+2] = hz; dhi[i+3] = hw;
    dlo[i+0] = __float2bfloat16(v.x - __bfloat162float(hx));
    dlo[i+1] = __float2bfloat16(v.y - __bfloat162float(hy));
    dlo[i+2] = __float2bfloat16(v.z - __bfloat162float(hz));
    dlo[i+3] = __float2bfloat16(v.w - __bfloat162float(hw));
}

// ---------------------------------------------------------------------------
// agT: C[z] = A[z/a_div] @ B[z]  (M=K=1024, N=DN) on mma.sync bf16, split x3.
// CTA tile 64 x DN, 8 warps (2m x 4n), K staged in 64-chunks.
// ---------------------------------------------------------------------------
template<int DN>
__global__ void __launch_bounds__(256) agT_kernel(
    const bf16* __restrict__ Bhi_g, const bf16* __restrict__ Blo_g,
    float* __restrict__ Call, int a_div, int c_perm)
{
    constexpr int AP = 72;            // A smem row pitch (bf16)
    constexpr int BP = DN + 8;        // B smem row pitch
    constexpr int WN = DN / 4;        // warp N extent
    constexpr int NB = WN / 8;        // n8 frags per warp
    constexpr int A_OFF = 0;          // Ahi
    constexpr int A_LO  = 64 * AP;    // Alo
    constexpr int B_OFF = 2 * 64 * AP;
    constexpr int B_LO  = B_OFF + 64 * BP;

    extern __shared__ bf16 sm[];
    const unsigned sbase = smem_u32(sm);

    const int tid  = threadIdx.x;
    const int wid  = tid >> 5, lane = tid & 31;
    const int mt   = blockIdx.x;                  // 16 M-tiles of 64
    const int z    = blockIdx.z;
    const int a_idx = z / a_div;
    const int cz   = c_perm ? ((z % a_div) * (gridDim.z / a_div) + a_idx) : z;
    const bf16* Bhi = Bhi_g + (size_t)z * NN * DN;
    const bf16* Blo = Blo_g + (size_t)z * NN * DN;
    float* C = Call + (size_t)cz * NN * DN;
    const bf16* Ahi = g_Ahi + ((size_t)a_idx * NN + (size_t)mt * 64) * NN;
    const bf16* Alo = g_Alo + ((size_t)a_idx * NN + (size_t)mt * 64) * NN;

    const int wm = wid >> 2, wn = wid & 3;        // warp grid 2 x 4
    const int m0w = wm * 32, n0w = wn * WN;

    float acc[2][NB][4];
    #pragma unroll
    for (int i = 0; i < 2; i++)
        #pragma unroll
        for (int j = 0; j < NB; j++)
            #pragma unroll
            for (int q = 0; q < 4; q++) acc[i][j][q] = 0.f;

    for (int ch = 0; ch < 16; ch++) {
        const int k0 = ch * 64;
        // ---- stage A tile (64 x 64, hi+lo) ----
        #pragma unroll
        for (int it = 0; it < 2; it++) {
            int item = tid + it * 256;            // 512 uint4 per split
            int r = item >> 3, c16 = item & 7;
            *(uint4*)(sm + A_OFF + r * AP + c16 * 8) =
                *(const uint4*)(Ahi + (size_t)r * NN + k0 + c16 * 8);
            *(uint4*)(sm + A_LO + r * AP + c16 * 8) =
                *(const uint4*)(Alo + (size_t)r * NN + k0 + c16 * 8);
        }
        // ---- stage B tile (64 x DN, hi+lo) ----
        constexpr int BU4 = 64 * DN / 8;
        #pragma unroll
        for (int it = 0; it < BU4 / 256; it++) {
            int item = tid + it * 256;
            int r = item / (DN / 8), c16 = item % (DN / 8);
            *(uint4*)(sm + B_OFF + r * BP + c16 * 8) =
                *(const uint4*)(Bhi + (size_t)(k0 + r) * DN + c16 * 8);
            *(uint4*)(sm + B_LO + r * BP + c16 * 8) =
                *(const uint4*)(Blo + (size_t)(k0 + r) * DN + c16 * 8);
        }
        __syncthreads();

        #pragma unroll
        for (int ks = 0; ks < 4; ks++) {
            const int kk = ks * 16;
            unsigned ahi[2][4], alo[2][4];
            #pragma unroll
            for (int mi = 0; mi < 2; mi++) {
                unsigned row = m0w + mi * 16 + (lane & 15);
                unsigned col = kk + (lane >> 4) * 8;
                ldm_x4(ahi[mi][0], ahi[mi][1], ahi[mi][2], ahi[mi][3],
                       sbase + 2u * (A_OFF + row * AP + col));
                ldm_x4(alo[mi][0], alo[mi][1], alo[mi][2], alo[mi][3],
                       sbase + 2u * (A_LO + row * AP + col));
            }
            unsigned bhi[NB][2], blo[NB][2];
            #pragma unroll
            for (int ni = 0; ni < NB; ni++) {
                unsigned row = kk + (lane & 15);
                unsigned col = n0w + ni * 8;
                ldm_x2t(bhi[ni][0], bhi[ni][1], sbase + 2u * (B_OFF + row * BP + col));
                ldm_x2t(blo[ni][0], blo[ni][1], sbase + 2u * (B_LO + row * BP + col));
            }
            #pragma unroll
            for (int mi = 0; mi < 2; mi++)
                #pragma unroll
                for (int ni = 0; ni < NB; ni++) {
                    mma_bf16(acc[mi][ni], ahi[mi], bhi[ni]);
                    mma_bf16(acc[mi][ni], ahi[mi], blo[ni]);
                    mma_bf16(acc[mi][ni], alo[mi], bhi[ni]);
                }
        }
        __syncthreads();
    }

    // ---- epilogue: fragment -> fp32 C ----
    const int g = lane >> 2, t = lane & 3;
    #pragma unroll
    for (int mi = 0; mi < 2; mi++) {
        int row = mt * 64 + m0w + mi * 16 + g;
        #pragma unroll
        for (int ni = 0; ni < NB; ni++) {
            int col = n0w + ni * 8 + t * 2;
            *(float2*)(C + (size_t)row * DN + col) =
                make_float2(acc[mi][ni][0], acc[mi][ni][1]);
            *(float2*)(C + (size_t)(row + 8) * DN + col) =
                make_float2(acc[mi][ni][2], acc[mi][ni][3]);
        }
    }
}

// ---------------------------------------------------------------------------
// pt_kernel: fused small GEMM + epilogue; optionally also emits bf16 hi/lo
// of the (fp32) result at the same [row][d] layout, for the next A-GEMM.
// ---------------------------------------------------------------------------
__global__ void __launch_bounds__(256) pt_kernel(
    const float* __restrict__ in0, int d0,
    const float* __restrict__ in1, int d1,
    const float* __restrict__ W, const float* __restrict__ bias,
    int Kd, int Dout,
    float* __restrict__ outp,
    int mode, int tstep,
    const float* __restrict__ aux0,
    const float* __restrict__ aux1,
    const float* __restrict__ obs_t,
    bf16* __restrict__ ohi, bf16* __restrict__ olo)
{
    __shared__ float Gs[64][65];
    __shared__ float Ws[64][64];

    const int row0 = blockIdx.x * 64;
    const int dc0  = blockIdx.y * 64;
    const int tid = threadIdx.x;
    const int ty = tid >> 4, tx = tid & 15;

    float acc[4][4] = {};

    for (int k0 = 0; k0 < Kd; k0 += 64) {
        const float* src; int stride, koff;
        if (k0 < d0) { src = in0; stride = d0; koff = k0; }
        else         { src = in1; stride = d1; koff = k0 - d0; }
        #pragma unroll
        for (int l = 0; l < 4; l++) {
            int f = tid + l * 256;
            int r = f >> 4, c4 = f & 15;
            float4 v = *(const float4*)(src + (size_t)(row0 + r) * stride + koff + c4*4);
            Gs[r][c4*4+0] = v.x; Gs[r][c4*4+1] = v.y;
            Gs[r][c4*4+2] = v.z; Gs[r][c4*4+3] = v.w;
        }
        #pragma unroll
        for (int l = 0; l < 4; l++) {
            int f = tid + l * 256;
            int r = f >> 4, c4 = f & 15;
            *(float4*)&Ws[r][c4*4] =
                *(const float4*)(W + (size_t)(k0 + r) * Dout + dc0 + c4*4);
        }
        __syncthreads();
        #pragma unroll
        for (int k = 0; k < 64; k++) {
            float a0 = Gs[ty*4+0][k], a1 = Gs[ty*4+1][k];
            float a2 = Gs[ty*4+2][k], a3 = Gs[ty*4+3][k];
            float4 b = *(const float4*)&Ws[k][tx*4];
            acc[0][0] += a0*b.x; acc[0][1] += a0*b.y; acc[0][2] += a0*b.z; acc[0][3] += a0*b.w;
            acc[1][0] += a1*b.x; acc[1][1] += a1*b.y; acc[1][2] += a1*b.z; acc[1][3] += a1*b.w;
            acc[2][0] += a2*b.x; acc[2][1] += a2*b.y; acc[2][2] += a2*b.z; acc[2][3] += a2*b.w;
            acc[3][0] += a3*b.x; acc[3][1] += a3*b.y; acc[3][2] += a3*b.z; acc[3][3] += a3*b.w;
        }
        __syncthreads();
    }

    const int dbase = dc0 + tx * 4;
    float4 bv = *(const float4*)(bias + dbase);
    float bb[4] = {bv.x, bv.y, bv.z, bv.w};

    #pragma unroll
    for (int i = 0; i < 4; i++) {
        int row = row0 + ty * 4 + i;
        #pragma unroll
        for (int j = 0; j < 4; j++) {
            int dg = dbase + j;
            float v = acc[i][j] + bb[j];
            size_t idx = (size_t)row * Dout + dg;
            float o;
            if (mode == 0) {
                o = tanhf(v);
            } else if (mode == 2) {
                o = aux0[idx] + v * DT_C;
            } else if (mode == 3) {
                o = 1.f / (1.f + expf(-v));
            } else if (mode == 4) {
                o = (1.f / (1.f + expf(-v))) * aux0[idx];
            } else if (mode == 5) {
                float c  = tanhf(v);
                float zz = aux0[idx];
                float h1 = aux1[idx];
                float ob = obs_t[row >> 10];
                float hv2 = (1.f - zz) * h1 + zz * c;
                o = h1 * (1.f - ob) + hv2 * ob;
            } else { // mode 6: out[b, t-1, n, dg]
                o = v;
                outp[((size_t)((row >> 10) * (TT - 1) + (tstep - 1)) * NN
                      + (row & (NN - 1))) * DIN + dg] = o;
                continue;
            }
            outp[idx] = o;
            if (ohi) {
                bf16 h = __float2bfloat16(o);
                ohi[idx] = h;
                olo[idx] = __float2bfloat16(o - __bfloat162float(h));
            }
        }
    }
}

// --------------------------- small utility kernels -------------------------
__global__ void __launch_bounds__(256) xmask_kernel(
    const float4* __restrict__ v, const float4* __restrict__ m)
{
    int i = blockIdx.x * 256 + threadIdx.x;
    float4 a = v[i], b = m[i];
    float x[4] = {a.x*b.x, a.y*b.y, a.z*b.z, a.w*b.w};
    bf16 hi[4], lo[4];
    #pragma unroll
    for (int j = 0; j < 4; j++) {
        hi[j] = __float2bfloat16(x[j]);
        lo[j] = __float2bfloat16(x[j] - __bfloat162float(hi[j]));
    }
    *(uint2*)&g_Xhi[(size_t)i*4] = *(uint2*)hi;
    *(uint2*)&g_Xlo[(size_t)i*4] = *(uint2*)lo;
}

__global__ void __launch_bounds__(256) inith_kernel(const float* __restrict__ h0)
{
    int i = blockIdx.x * 256 + threadIdx.x;
    float v = h0[i & (DR - 1)];
    g_H[i] = v;
    bf16 h = __float2bfloat16(v);
    g_Hhi[i] = h;
    g_Hlo[i] = __float2bfloat16(v - __bfloat162float(h));
}

__global__ void __launch_bounds__(256) obs_kernel(
    const float* __restrict__ masks, float* __restrict__ obs)
{
    __shared__ float sh[256];
    int bt = blockIdx.x;
    const float* p = masks + (size_t)bt * (NN * DIN);
    float s = 0.f;
    for (int i = threadIdx.x; i < NN * DIN; i += 256) s += fabsf(p[i]);
    sh[threadIdx.x] = s; __syncthreads();
    for (int o = 128; o > 0; o >>= 1) {
        if (threadIdx.x < o) sh[threadIdx.x] += sh[threadIdx.x + o];
        __syncthreads();
    }
    if (threadIdx.x == 0) {
        int b = bt >> 5, t = bt & 31;
        obs[t * BB + b] = (sh[0] > 1e-4f) ? 1.f : 0.f;
    }
}

// ------------------------------- launch ------------------------------------
extern "C" void kernel_launch(void* const* d_in, const int* in_sizes, int n_in,
                              void* d_out, int out_size)
{
    const float* values = (const float*)d_in[0];
    const float* masks  = (const float*)d_in[1];
    const float* A      = (const float*)d_in[2];
    const float* h0     = (const float*)d_in[3];
    const float* W0  = (const float*)d_in[4];  const float* b0v = (const float*)d_in[5];
    const float* W1  = (const float*)d_in[6];  const float* b1v = (const float*)d_in[7];
    const float* Wou = (const float*)d_in[8];  const float* bou = (const float*)d_in[9];
    const float* Wz  = (const float*)d_in[10]; const float* bz  = (const float*)d_in[11];
    const float* Wr  = (const float*)d_in[12]; const float* br  = (const float*)d_in[13];
    const float* Wh  = (const float*)d_in[14]; const float* bh  = (const float*)d_in[15];
    const float* Wo  = (const float*)d_in[16]; const float* bo  = (const float*)d_in[17];
    float* out = (float*)d_out;

    float *AX, *H, *HV1, *U, *G, *Z, *RH, *OBS;
    bf16 *Xhi, *Xlo, *Hhi, *Hlo, *HV1hi, *HV1lo, *Uhi, *Ulo, *RHhi, *RHlo;
    cudaGetSymbolAddress((void**)&AX,  g_AX);
    cudaGetSymbolAddress((void**)&H,   g_H);
    cudaGetSymbolAddress((void**)&HV1, g_HV1);
    cudaGetSymbolAddress((void**)&U,   g_U);
    cudaGetSymbolAddress((void**)&G,   g_G);
    cudaGetSymbolAddress((void**)&Z,   g_Z);
    cudaGetSymbolAddress((void**)&RH,  g_RH);
    cudaGetSymbolAddress((void**)&OBS, g_OBS);
    cudaGetSymbolAddress((void**)&Xhi, g_Xhi);   cudaGetSymbolAddress((void**)&Xlo, g_Xlo);
    cudaGetSymbolAddress((void**)&Hhi, g_Hhi);   cudaGetSymbolAddress((void**)&Hlo, g_Hlo);
    cudaGetSymbolAddress((void**)&HV1hi, g_HV1hi); cudaGetSymbolAddress((void**)&HV1lo, g_HV1lo);
    cudaGetSymbolAddress((void**)&Uhi, g_Uhi);   cudaGetSymbolAddress((void**)&Ulo, g_Ulo);
    cudaGetSymbolAddress((void**)&RHhi, g_RHhi); cudaGetSymbolAddress((void**)&RHlo, g_RHlo);

    // dynamic smem: A(2*64*72) + B(2*64*(DN+8)) bf16
    const int SM128 = (2*64*72 + 2*64*136) * 2;   // 53248 B
    const int SM64  = (2*64*72 + 2*64*72)  * 2;   // 36864 B
    cudaFuncSetAttribute(agT_kernel<128>, cudaFuncAttributeMaxDynamicSharedMemorySize, SM128);
    cudaFuncSetAttribute(agT_kernel<64>,  cudaFuncAttributeMaxDynamicSharedMemorySize, SM64);

    // --- precompute ---
    convA_kernel<<<BB*NN, 256>>>(A);
    xmask_kernel<<<(BB*TT*NN*DIN)/4/256, 256>>>(
        (const float4*)values, (const float4*)masks);
    obs_kernel<<<BB*TT, 256>>>(masks, OBS);
    // AX[t,b] = A[b] @ X[b,t]
    agT_kernel<DIN><<<dim3(16, 1, BB*TT), 256, SM64>>>(Xhi, Xlo, AX, TT, 1);
    inith_kernel<<<(BB*NN*DR)/256, 256>>>(h0);

    auto AG = [&](const bf16* bhi, const bf16* blo, float* Cout) {
        agT_kernel<DR><<<dim3(16, 1, BB), 256, SM128>>>(bhi, blo, Cout, 1, 0);
    };
    auto PT = [&](const float* in0, int d0, const float* in1, int d1,
                  const float* W, const float* bias, int Kd, int Dout, float* o,
                  int mode, int t, const float* a0, const float* a1, const float* ob,
                  bf16* ohi, bf16* olo) {
        pt_kernel<<<dim3((BB*NN)/64, Dout/64), 256>>>(
            in0, d0, in1, d1, W, bias, Kd, Dout, o, mode, t, a0, a1, ob, ohi, olo);
    };
    // ODE: hout = hin + ode(hin)*DT ; hout gets bf16 hi/lo at (ohi, olo)
    auto ODE = [&](const float* hin, const bf16* hinhi, const bf16* hinlo,
                   float* hout, bf16* ohi, bf16* olo) {
        AG(hinhi, hinlo, G);
        PT(G, DR, nullptr, 0, W0,  b0v, DR, DR, U, 0, 0, nullptr, nullptr, nullptr, Uhi, Ulo);
        AG(Uhi, Ulo, G);
        PT(G, DR, nullptr, 0, W1,  b1v, DR, DR, U, 0, 0, nullptr, nullptr, nullptr, Uhi, Ulo);
        AG(Uhi, Ulo, G);
        PT(G, DR, nullptr, 0, Wou, bou, DR, DR, hout, 2, 0, hin, nullptr, nullptr, ohi, olo);
    };

    // iteration 0: h = h + ode(h)*DT
    ODE(H, Hhi, Hlo, H, Hhi, Hlo);

    for (int t = 0; t < TT; t++) {
        ODE(H, Hhi, Hlo, HV1, HV1hi, HV1lo);
        if (t >= 1)
            PT(HV1, DR, nullptr, 0, Wo, bo, DR, DIN, out, 6, t,
               nullptr, nullptr, nullptr, nullptr, nullptr);
        if (t < TT - 1) {
            AG(HV1hi, HV1lo, G);
            const float* AXt = AX + (size_t)t * BB * NN * DIN;
            PT(AXt, DIN, G, DR, Wz, bz, DIN + DR, DR, Z,  3, t,
               nullptr, nullptr, nullptr, nullptr, nullptr);
            PT(AXt, DIN, G, DR, Wr, br, DIN + DR, DR, RH, 4, t,
               HV1, nullptr, nullptr, RHhi, RHlo);
            AG(RHhi, RHlo, G);
            PT(AXt, DIN, G, DR, Wh, bh, DIN + DR, DR, H,  5, t,
               Z, HV1, OBS + t * BB, Hhi, Hlo);
        }
    }
}